// round 16
// baseline (speedup 1.0000x reference)
#include <cuda_runtime.h>

// ---------------------------------------------------------------------------
// Persistent-kernel WaveNet stack (proven R13 k_persist) + optimized final
// head: 256-thread blocks, up-projection packed as f32x2 over output pairs
// with transposed-paired weights in smem. Flag reset folded into k_final.
// (Resubmission of R14 — previous bench failed at device acquisition, an
// infra flake preceding any kernel execution.)
// ---------------------------------------------------------------------------

#define S3   3
#define BB   8
#define CH   16
#define GC   32
#define LL   4096
#define RR   24          // S3*BB rows
#define TILE 128
#define NTHR 256
#define NSTG 33
#define NCHK 16          // chunks per row (256 positions each)
#define NITEM (NSTG * RR * NCHK)

typedef unsigned long long ull;

__device__ __forceinline__ ull dup2(float a) {
    ull r; asm("mov.b64 %0, {%1,%1};" : "=l"(r) : "f"(a)); return r;
}
__device__ __forceinline__ void upk(ull v, float &a, float &b) {
    asm("mov.b64 {%0,%1}, %2;" : "=f"(a), "=f"(b) : "l"(v));
}
__device__ __forceinline__ ull pk(float a, float b) {
    ull r; asm("mov.b64 %0, {%1,%2};" : "=l"(r) : "f"(a), "f"(b)); return r;
}
__device__ __forceinline__ ull f2fma(ull a, ull b, ull c) {
    ull r; asm("fma.rn.f32x2 %0, %1, %2, %3;" : "=l"(r) : "l"(a), "l"(b), "l"(c)); return r;
}
__device__ __forceinline__ float tanhap(float x) {
    float r; asm("tanh.approx.f32 %0, %1;" : "=f"(r) : "f"(x)); return r;
}
__device__ __forceinline__ float sigap(float x) {
    return fmaf(tanhap(x * 0.5f), 0.5f, 0.5f);
}
__device__ __forceinline__ int ld_acq(const int* p) {
    int v; asm volatile("ld.acquire.gpu.global.b32 %0, [%1];" : "=r"(v) : "l"(p) : "memory");
    return v;
}
__device__ __forceinline__ void st_rel(int* p, int v) {
    asm volatile("st.release.gpu.global.b32 [%0], %1;" :: "l"(p), "r"(v) : "memory");
}

// Residual stream 4-buffer ring + skip accumulator, [row][c][l]
__device__ float g_X4[4][RR * CH * LL];
__device__ float g_SK[RR * CH * LL];
__device__ int   g_flag[NITEM];      // zero-initialized at module load

// Shared layout (float offsets). Dup (ull) regions store each scalar twice.
#define O_WFD 0          // 2048  [oc][c][tap] dup
#define O_WGD 2048       // 2048
#define O_W2T 4096       // 1024  transposed [k][o] dup
#define O_W1D 5120       // 512   [o][c] dup
#define O_BFD 5632       // 64
#define O_BGD 5696       // 64
#define O_B2D 5760       // 32
#define O_B1D 5792       // 32
#define O_H   5824       // small: 16ch x 384 | large: 3 windows x 16ch x 128 (both 6144)
#define O_Z   11968      // 32 ch x 128 = 4096
#define SM_FLOATS 16064  // 64256 bytes

// ---------------------------------------------------------------------------
__global__ void __launch_bounds__(NTHR, 3) k_persist(
        int G,
        const float* __restrict__ xin,
        const float* __restrict__ c1fw, const float* __restrict__ c1fb,
        const float* __restrict__ c1pw, const float* __restrict__ c1pb,
        const float* __restrict__ cfw, const float* __restrict__ cfb,
        const float* __restrict__ cgw, const float* __restrict__ cgb,
        const float* __restrict__ c2w, const float* __restrict__ c2b) {
    extern __shared__ float sm[];
    int tid = threadIdx.x;

    for (int n = blockIdx.x; n < NITEM; n += G) {
        int stage = n / (RR * NCHK);
        int m = n - stage * (RR * NCHK);
        int row = m >> 4, chunk = m & 15;
        int s = row >> 3, bb = row & 7;
        int d = 1 << (stage % 11);
        int a = d >> 1;
        int t0 = chunk << 8;                 // 256 positions per chunk
        int first = (stage == 0);
        int small = (d <= 128);
        const float* Xsrc = g_X4[(stage + 3) & 3];
        float* Xdst       = g_X4[stage & 3];

        // ---- stage weights -> smem (duplicated, vectorized staging) ----
        {
            int wb = s * 33 + stage;
            const float* fsrc = cfw + wb * 1024;
            const float* gsrc = cgw + wb * 1024;
            ull* WFD = (ull*)(sm + O_WFD);
            ull* WGD = (ull*)(sm + O_WGD);
            {
                float4 f4 = *(const float4*)(fsrc + tid * 4);
                ulonglong2 u0, u1;
                u0.x = dup2(f4.x); u0.y = dup2(f4.y);
                u1.x = dup2(f4.z); u1.y = dup2(f4.w);
                *(ulonglong2*)(WFD + tid * 4)     = u0;
                *(ulonglong2*)(WFD + tid * 4 + 2) = u1;
                float4 g4 = *(const float4*)(gsrc + tid * 4);
                u0.x = dup2(g4.x); u0.y = dup2(g4.y);
                u1.x = dup2(g4.z); u1.y = dup2(g4.w);
                *(ulonglong2*)(WGD + tid * 4)     = u0;
                *(ulonglong2*)(WGD + tid * 4 + 2) = u1;
            }
            const float* w2src = c2w + wb * 512;
            ull* W2T = (ull*)(sm + O_W2T);
#pragma unroll
            for (int e = 0; e < 2; e++) {
                int idx = tid + e * 256;
                int k = idx >> 4, o = idx & 15;
                W2T[idx] = dup2(w2src[o * 32 + k]);
            }
            ull* W1D = (ull*)(sm + O_W1D);
            if (first) {
                if (tid < 16) {
                    W1D[tid] = dup2(c1fw[s * 16 + tid]);
                    ((ull*)(sm + O_B1D))[tid] = dup2(c1fb[s * 16 + tid]);
                }
            } else {
                int pbase = (s * 32 + (stage - 1));
                W1D[tid] = dup2(c1pw[pbase * 256 + tid]);
                if (tid < 16) ((ull*)(sm + O_B1D))[tid] = dup2(c1pb[pbase * 16 + tid]);
            }
            if (tid < 32) {
                ((ull*)(sm + O_BFD))[tid] = dup2(cfb[wb * 32 + tid]);
                ((ull*)(sm + O_BGD))[tid] = dup2(cgb[wb * 32 + tid]);
            }
            if (tid < 16) ((ull*)(sm + O_B2D))[tid] = dup2(c2b[wb * 16 + tid]);
        }

        // ---- dependency waits: PARALLEL flag polling by warp-0 lanes ----
        if (tid < 32) {
            int myflag = -1;
            if (!first && tid < 8) {
                // RAW on stage-1: lanes 0..7
                int lo_pos = t0 - a;
                int hi_pos = t0 + 255 + (d - a);
                if (lo_pos < 0) lo_pos = 0;
                if (hi_pos > LL - 1) hi_pos = LL - 1;
                int lo = lo_pos >> 8, hi = hi_pos >> 8;
                if (lo + tid <= hi)
                    myflag = ((stage - 1) * RR + row) * NCHK + lo + tid;
            } else if (stage >= 4 && tid >= 8 && tid < 24) {
                // WAR: stage-3 readers of buf[stage&3]: lanes 8..23
                int d3 = 1 << ((stage - 3) % 11);
                int a3 = d3 >> 1;
                int lo_pos = t0 - 255 - (d3 - a3);
                int hi_pos = t0 + 255 + a3;
                if (lo_pos < 0) lo_pos = 0;
                if (hi_pos > LL - 1) hi_pos = LL - 1;
                int lo = lo_pos >> 8, hi = hi_pos >> 8;
                int k = tid - 8;
                if (lo + k <= hi)
                    myflag = ((stage - 3) * RR + row) * NCHK + lo + k;
            } else if (stage >= 4 && tid == 24) {
                // WAW: stage-4 writer of the same chunk
                myflag = ((stage - 4) * RR + row) * NCHK + chunk;
            }
            if (myflag >= 0) {
                while (ld_acq(&g_flag[myflag]) == 0) __nanosleep(128);
            }
        }
        __syncthreads();

        if (small) {
            // ================= SMALL-d PATH (d <= 128) =================
            int npairs = (257 + d) >> 1;   // ceil((256+d)/2) <= 192
            if (tid < npairs) {
                int p = tid * 2;
                int pos0 = t0 - a + p;
                bool in0 = (unsigned)pos0 < LL;
                bool in1 = (unsigned)(pos0 + 1) < LL;
                float* hdst = sm + O_H + p;
                const ull* W1D = (const ull*)(sm + O_W1D);
                const ull* B1D = (const ull*)(sm + O_B1D);
                if (first) {
                    float x0 = in0 ? xin[(bb * LL + pos0) * 3 + s] : 0.f;
                    float x1 = in1 ? xin[(bb * LL + pos0 + 1) * 3 + s] : 0.f;
                    ull xv = pk(x0, x1);
#pragma unroll
                    for (int o = 0; o < 16; o++) {
                        ull r = f2fma(xv, W1D[o], B1D[o]);
                        float r0, r1; upk(r, r0, r1);
                        hdst[o * 384]     = in0 ? fmaxf(r0, 0.f) : 0.f;
                        hdst[o * 384 + 1] = in1 ? fmaxf(r1, 0.f) : 0.f;
                    }
                } else {
                    const float* Xr = Xsrc + row * CH * LL;
                    ull xv[16];
#pragma unroll
                    for (int c = 0; c < 16; c++) {
                        float x0 = in0 ? __ldcg(Xr + c * LL + pos0) : 0.f;
                        float x1 = in1 ? __ldcg(Xr + c * LL + pos0 + 1) : 0.f;
                        xv[c] = pk(x0, x1);
                    }
#pragma unroll
                    for (int o = 0; o < 16; o++) {
                        ull acc = B1D[o];
#pragma unroll
                        for (int c = 0; c < 16; c++)
                            acc = f2fma(xv[c], W1D[o * 16 + c], acc);
                        float r0, r1; upk(acc, r0, r1);
                        hdst[o * 384]     = in0 ? fmaxf(r0, 0.f) : 0.f;
                        hdst[o * 384 + 1] = in1 ? fmaxf(r1, 0.f) : 0.f;
                    }
                }
            }
            __syncthreads();

            int q = tid >> 5, pg = tid & 31;
            int ocb = q * 4, p4 = pg * 4;
            const ull* WF = (const ull*)(sm + O_WFD);
            const ull* WG = (const ull*)(sm + O_WGD);

            for (int sub = 0; sub < 2; sub++) {
                int soff = sub * 128;
                ull fA[4][2], gA[4][2];
#pragma unroll
                for (int ii = 0; ii < 4; ii++) {
                    ull fb = ((const ull*)(sm + O_BFD))[ocb + ii];
                    ull gb = ((const ull*)(sm + O_BGD))[ocb + ii];
                    fA[ii][0] = fb; fA[ii][1] = fb;
                    gA[ii][0] = gb; gA[ii][1] = gb;
                }
                if (d >= 4) {
#pragma unroll
                    for (int c = 0; c < 16; c++) {
                        const float* hb = sm + O_H + c * 384 + soff;
                        ulonglong2 hl = *(const ulonglong2*)(hb + p4);
                        ulonglong2 hr = *(const ulonglong2*)(hb + p4 + d);
#pragma unroll
                        for (int ii = 0; ii < 4; ii++) {
                            int wbase = ((ocb + ii) * 16 + c) * 2;
                            ulonglong2 wf = *(const ulonglong2*)(WF + wbase);
                            ulonglong2 wg = *(const ulonglong2*)(WG + wbase);
                            fA[ii][0] = f2fma(hl.x, wf.x, fA[ii][0]);
                            fA[ii][0] = f2fma(hr.x, wf.y, fA[ii][0]);
                            fA[ii][1] = f2fma(hl.y, wf.x, fA[ii][1]);
                            fA[ii][1] = f2fma(hr.y, wf.y, fA[ii][1]);
                            gA[ii][0] = f2fma(hl.x, wg.x, gA[ii][0]);
                            gA[ii][0] = f2fma(hr.x, wg.y, gA[ii][0]);
                            gA[ii][1] = f2fma(hl.y, wg.x, gA[ii][1]);
                            gA[ii][1] = f2fma(hr.y, wg.y, gA[ii][1]);
                        }
                    }
                } else {
#pragma unroll
                    for (int c = 0; c < 16; c++) {
                        const float* hb = sm + O_H + c * 384 + soff;
                        ulonglong2 hl = *(const ulonglong2*)(hb + p4);
                        ull b4 = *(const ull*)(hb + p4 + 4);
                        ulonglong2 hr;
                        if (d == 2) {
                            hr.x = hl.y; hr.y = b4;
                        } else {
                            float f0, f1, f2, f3, f4, f5;
                            upk(hl.x, f0, f1); upk(hl.y, f2, f3); upk(b4, f4, f5);
                            hr.x = pk(f1, f2); hr.y = pk(f3, f4);
                        }
#pragma unroll
                        for (int ii = 0; ii < 4; ii++) {
                            int wbase = ((ocb + ii) * 16 + c) * 2;
                            ulonglong2 wf = *(const ulonglong2*)(WF + wbase);
                            ulonglong2 wg = *(const ulonglong2*)(WG + wbase);
                            fA[ii][0] = f2fma(hl.x, wf.x, fA[ii][0]);
                            fA[ii][0] = f2fma(hr.x, wf.y, fA[ii][0]);
                            fA[ii][1] = f2fma(hl.y, wf.x, fA[ii][1]);
                            fA[ii][1] = f2fma(hr.y, wf.y, fA[ii][1]);
                            gA[ii][0] = f2fma(hl.x, wg.x, gA[ii][0]);
                            gA[ii][0] = f2fma(hr.x, wg.y, gA[ii][0]);
                            gA[ii][1] = f2fma(hl.y, wg.x, gA[ii][1]);
                            gA[ii][1] = f2fma(hr.y, wg.y, gA[ii][1]);
                        }
                    }
                }
#pragma unroll
                for (int ii = 0; ii < 4; ii++) {
                    float* zp = sm + O_Z + (ocb + ii) * 128 + p4;
                    float f0, f1, f2, f3, g0, g1, g2, g3;
                    upk(fA[ii][0], f0, f1); upk(fA[ii][1], f2, f3);
                    upk(gA[ii][0], g0, g1); upk(gA[ii][1], g2, g3);
                    float4 zv;
                    zv.x = tanhap(f0) * sigap(g0);
                    zv.y = tanhap(f1) * sigap(g1);
                    zv.z = tanhap(f2) * sigap(g2);
                    zv.w = tanhap(f3) * sigap(g3);
                    *(float4*)zp = zv;
                }
                __syncthreads();

                int o0 = q * 2;
                const ull* W2T = (const ull*)(sm + O_W2T);
                ull acc[2][2];
#pragma unroll
                for (int oi = 0; oi < 2; oi++) {
                    ull bv = ((const ull*)(sm + O_B2D))[o0 + oi];
                    acc[oi][0] = bv; acc[oi][1] = bv;
                }
#pragma unroll 8
                for (int k = 0; k < 32; k++) {
                    ulonglong2 zv = *(const ulonglong2*)(sm + O_Z + k * 128 + p4);
                    ulonglong2 w = *(const ulonglong2*)(W2T + k * 16 + o0);
                    acc[0][0] = f2fma(zv.x, w.x, acc[0][0]);
                    acc[0][1] = f2fma(zv.y, w.x, acc[0][1]);
                    acc[1][0] = f2fma(zv.x, w.y, acc[1][0]);
                    acc[1][1] = f2fma(zv.y, w.y, acc[1][1]);
                }
                float* SKg = g_SK + row * CH * LL;
#pragma unroll
                for (int oi = 0; oi < 2; oi++) {
                    int o = o0 + oi;
                    const float* hc = sm + O_H + o * 384 + soff + p4 + a;
                    float h0, h1, h2, h3;
                    if (a & 1) {
                        h0 = hc[0]; h1 = hc[1]; h2 = hc[2]; h3 = hc[3];
                    } else {
                        float u0a, u0b, u1a, u1b;
                        upk(*(const ull*)hc, u0a, u0b);
                        upk(*(const ull*)(hc + 2), u1a, u1b);
                        h0 = u0a; h1 = u0b; h2 = u1a; h3 = u1b;
                    }
                    float r0, r1, r2, r3;
                    upk(acc[oi][0], r0, r1); upk(acc[oi][1], r2, r3);
                    r0 = fmaxf(r0, 0.f); r1 = fmaxf(r1, 0.f);
                    r2 = fmaxf(r2, 0.f); r3 = fmaxf(r3, 0.f);
                    int gidx = (row * CH + o) * LL + t0 + soff + p4;
                    if (stage != NSTG - 1) {
                        float4 xv = make_float4(h0 + r0, h1 + r1, h2 + r2, h3 + r3);
                        __stcg((float4*)(Xdst + gidx), xv);
                    }
                    float* so = SKg + o * LL + t0 + soff + p4;
                    if (first) {
                        __stcg((float4*)so, make_float4(r0, r1, r2, r3));
                    } else {
                        float4 old = __ldcg((const float4*)so);
                        __stcg((float4*)so, make_float4(old.x + r0, old.y + r1, old.z + r2, old.w + r3));
                    }
                }
                __syncthreads();
            }
        } else {
            // ================= LARGE-d PATH (d > 128): per-tile 3 windows ======
            for (int sub = 0; sub < 2; sub++) {
                int t0s = t0 + sub * 128;
                if (tid < 192) {
                    int w = tid >> 6;
                    int p = (tid & 63) * 2;
                    int wstart = (w == 0) ? t0s - a : (w == 1) ? t0s + d - a : t0s;
                    int pos0 = wstart + p;
                    bool in0 = (unsigned)pos0 < LL;
                    bool in1 = (unsigned)(pos0 + 1) < LL;
                    float* hdst = sm + O_H + w * 2048 + p;
                    const ull* W1D = (const ull*)(sm + O_W1D);
                    const ull* B1D = (const ull*)(sm + O_B1D);
                    const float* Xr = Xsrc + row * CH * LL;
                    ull xv[16];
#pragma unroll
                    for (int c = 0; c < 16; c++) {
                        float x0 = in0 ? __ldcg(Xr + c * LL + pos0) : 0.f;
                        float x1 = in1 ? __ldcg(Xr + c * LL + pos0 + 1) : 0.f;
                        xv[c] = pk(x0, x1);
                    }
#pragma unroll
                    for (int o = 0; o < 16; o++) {
                        ull acc = B1D[o];
#pragma unroll
                        for (int c = 0; c < 16; c++)
                            acc = f2fma(xv[c], W1D[o * 16 + c], acc);
                        float r0, r1; upk(acc, r0, r1);
                        hdst[o * 128]     = in0 ? fmaxf(r0, 0.f) : 0.f;
                        hdst[o * 128 + 1] = in1 ? fmaxf(r1, 0.f) : 0.f;
                    }
                }
                __syncthreads();

                int q = tid >> 5, pg = tid & 31;
                int ocb = q * 4, p4 = pg * 4;
                const ull* WF = (const ull*)(sm + O_WFD);
                const ull* WG = (const ull*)(sm + O_WGD);

                ull fA[4][2], gA[4][2];
#pragma unroll
                for (int ii = 0; ii < 4; ii++) {
                    ull fb = ((const ull*)(sm + O_BFD))[ocb + ii];
                    ull gb = ((const ull*)(sm + O_BGD))[ocb + ii];
                    fA[ii][0] = fb; fA[ii][1] = fb;
                    gA[ii][0] = gb; gA[ii][1] = gb;
                }
#pragma unroll
                for (int c = 0; c < 16; c++) {
                    ulonglong2 hl = *(const ulonglong2*)(sm + O_H + c * 128 + p4);
                    ulonglong2 hr = *(const ulonglong2*)(sm + O_H + 2048 + c * 128 + p4);
#pragma unroll
                    for (int ii = 0; ii < 4; ii++) {
                        int wbase = ((ocb + ii) * 16 + c) * 2;
                        ulonglong2 wf = *(const ulonglong2*)(WF + wbase);
                        ulonglong2 wg = *(const ulonglong2*)(WG + wbase);
                        fA[ii][0] = f2fma(hl.x, wf.x, fA[ii][0]);
                        fA[ii][0] = f2fma(hr.x, wf.y, fA[ii][0]);
                        fA[ii][1] = f2fma(hl.y, wf.x, fA[ii][1]);
                        fA[ii][1] = f2fma(hr.y, wf.y, fA[ii][1]);
                        gA[ii][0] = f2fma(hl.x, wg.x, gA[ii][0]);
                        gA[ii][0] = f2fma(hr.x, wg.y, gA[ii][0]);
                        gA[ii][1] = f2fma(hl.y, wg.x, gA[ii][1]);
                        gA[ii][1] = f2fma(hr.y, wg.y, gA[ii][1]);
                    }
                }
#pragma unroll
                for (int ii = 0; ii < 4; ii++) {
                    float* zp = sm + O_Z + (ocb + ii) * 128 + p4;
                    float f0, f1, f2, f3, g0, g1, g2, g3;
                    upk(fA[ii][0], f0, f1); upk(fA[ii][1], f2, f3);
                    upk(gA[ii][0], g0, g1); upk(gA[ii][1], g2, g3);
                    float4 zv;
                    zv.x = tanhap(f0) * sigap(g0);
                    zv.y = tanhap(f1) * sigap(g1);
                    zv.z = tanhap(f2) * sigap(g2);
                    zv.w = tanhap(f3) * sigap(g3);
                    *(float4*)zp = zv;
                }
                __syncthreads();

                int o0 = q * 2;
                const ull* W2T = (const ull*)(sm + O_W2T);
                ull acc[2][2];
#pragma unroll
                for (int oi = 0; oi < 2; oi++) {
                    ull bv = ((const ull*)(sm + O_B2D))[o0 + oi];
                    acc[oi][0] = bv; acc[oi][1] = bv;
                }
#pragma unroll 8
                for (int k = 0; k < 32; k++) {
                    ulonglong2 zv = *(const ulonglong2*)(sm + O_Z + k * 128 + p4);
                    ulonglong2 w = *(const ulonglong2*)(W2T + k * 16 + o0);
                    acc[0][0] = f2fma(zv.x, w.x, acc[0][0]);
                    acc[0][1] = f2fma(zv.y, w.x, acc[0][1]);
                    acc[1][0] = f2fma(zv.x, w.y, acc[1][0]);
                    acc[1][1] = f2fma(zv.y, w.y, acc[1][1]);
                }
                float* SKg = g_SK + row * CH * LL;
#pragma unroll
                for (int oi = 0; oi < 2; oi++) {
                    int o = o0 + oi;
                    float4 hv = *(const float4*)(sm + O_H + 4096 + o * 128 + p4);
                    float r0, r1, r2, r3;
                    upk(acc[oi][0], r0, r1); upk(acc[oi][1], r2, r3);
                    r0 = fmaxf(r0, 0.f); r1 = fmaxf(r1, 0.f);
                    r2 = fmaxf(r2, 0.f); r3 = fmaxf(r3, 0.f);
                    if (stage != NSTG - 1) {
                        float4 xv = make_float4(hv.x + r0, hv.y + r1, hv.z + r2, hv.w + r3);
                        __stcg((float4*)(Xdst + (row * CH + o) * LL + t0s + p4), xv);
                    }
                    float* so = SKg + o * LL + t0s + p4;
                    float4 old = __ldcg((const float4*)so);
                    __stcg((float4*)so, make_float4(old.x + r0, old.y + r1, old.z + r2, old.w + r3));
                }
                __syncthreads();
            }
        }

        // ---- publish ----
        if (tid == 0) st_rel(&g_flag[(stage * RR + row) * NCHK + chunk], 1);
    }
}

// ---------------------------------------------------------------------------
// PinSage + final head: 256 threads/block, up-projection packed over o-pairs.
// Also resets dependency flags for the next graph replay.
// ---------------------------------------------------------------------------
__global__ void __launch_bounds__(256) k_final(const float* __restrict__ n1w,
                                               const float* __restrict__ n1b,
                                               const float* __restrict__ n2w,
                                               const float* __restrict__ n2b,
                                               const float* __restrict__ upw,
                                               const float* __restrict__ upb,
                                               const float* __restrict__ fw,
                                               const float* __restrict__ fb,
                                               float* __restrict__ out) {
    __shared__ float s_n1w[768], s_n2w[768], s_n1b[48], s_n2b[48];
    __shared__ ull  s_upwT[3072];   // [s][c(32)][opair(32)]: pk(w[2j][c], w[2j+1][c])
    __shared__ ull  s_upbP[96];     // [s][opair]
    __shared__ float s_fw[64], s_fb;
    int tid = threadIdx.x;
    int gi = blockIdx.x * 256 + tid;

    // reset dependency flags for the next replay
    if (gi < NITEM) g_flag[gi] = 0;

    for (int idx = tid; idx < 768; idx += 256) { s_n1w[idx] = n1w[idx]; s_n2w[idx] = n2w[idx]; }
    for (int idx = tid; idx < 3072; idx += 256) {
        int s = idx >> 10, r = idx & 1023;
        int c = r >> 5, j = r & 31;
        s_upwT[idx] = pk(upw[(s * 64 + 2 * j) * 32 + c], upw[(s * 64 + 2 * j + 1) * 32 + c]);
    }
    if (tid < 96) s_upbP[tid] = pk(upb[2 * tid], upb[2 * tid + 1]);
    if (tid < 48) { s_n1b[tid] = n1b[tid]; s_n2b[tid] = n2b[tid]; }
    if (tid < 64) s_fw[tid] = fw[tid];
    if (tid == 0) s_fb = fb[0];
    __syncthreads();

    int b = gi >> 12, l = gi & 4095;

    float F[3][16];
#pragma unroll
    for (int s = 0; s < 3; s++) {
        const float* sk = g_SK + (s * 8 + b) * CH * LL;
#pragma unroll
        for (int c = 0; c < 16; c++) F[s][c] = fmaxf(sk[c * LL + l], 0.f);
    }

    float m[64];
#pragma unroll
    for (int o = 0; o < 64; o++) m[o] = 0.f;

#pragma unroll
    for (int s = 0; s < 3; s++) {
        int n1 = (s == 0) ? 1 : 0;
        int n2 = (s == 2) ? 1 : 2;
        float nb[16];
#pragma unroll
        for (int o = 0; o < 16; o++) {
            float a1 = s_n1b[s * 16 + o], a2 = s_n2b[s * 16 + o];
#pragma unroll
            for (int c = 0; c < 16; c++) {
                a1 = fmaf(s_n1w[(s * 16 + o) * 16 + c], F[n1][c], a1);
                a2 = fmaf(s_n2w[(s * 16 + o) * 16 + c], F[n2][c], a2);
            }
            nb[o] = fmaxf(fmaxf(a1, 0.f), fmaxf(a2, 0.f));
        }
        // packed up-projection: u[j] covers outputs (2j, 2j+1); per-output
        // accumulation order preserved (bias, c=0..15 on F, c=0..15 on nb)
        ull u[32];
        const ull* WT = s_upwT + s * 1024;
#pragma unroll
        for (int j = 0; j < 32; j++) u[j] = s_upbP[s * 32 + j];
#pragma unroll
        for (int c = 0; c < 16; c++) {
            ull xd = dup2(F[s][c]);
            const ull* wr = WT + c * 32;
#pragma unroll
            for (int j = 0; j < 32; j++) u[j] = f2fma(xd, wr[j], u[j]);
        }
#pragma unroll
        for (int c = 0; c < 16; c++) {
            ull xd = dup2(nb[c]);
            const ull* wr = WT + (16 + c) * 32;
#pragma unroll
            for (int j = 0; j < 32; j++) u[j] = f2fma(xd, wr[j], u[j]);
        }
#pragma unroll
        for (int j = 0; j < 32; j++) {
            float u0, u1; upk(u[j], u0, u1);
            m[2 * j]     = fmaxf(m[2 * j],     fmaxf(u0, 0.f));
            m[2 * j + 1] = fmaxf(m[2 * j + 1], fmaxf(u1, 0.f));
        }
    }
    float logit = s_fb;
#pragma unroll
    for (int o = 0; o < 64; o++) logit = fmaf(s_fw[o], m[o], logit);
    out[gi] = fmaf(tanhap(logit * 0.5f), 0.5f, 0.5f);
}

// ---------------------------------------------------------------------------
extern "C" void kernel_launch(void* const* d_in, const int* in_sizes, int n_in,
                              void* d_out, int out_size) {
    const float* xin  = (const float*)d_in[0];
    const float* c1fw = (const float*)d_in[1];
    const float* c1fb = (const float*)d_in[2];
    const float* c1pw = (const float*)d_in[3];
    const float* c1pb = (const float*)d_in[4];
    const float* cfw  = (const float*)d_in[5];
    const float* cfb  = (const float*)d_in[6];
    const float* cgw  = (const float*)d_in[7];
    const float* cgb  = (const float*)d_in[8];
    const float* c2w  = (const float*)d_in[9];
    const float* c2b  = (const float*)d_in[10];
    const float* n1w  = (const float*)d_in[11];
    const float* n1b  = (const float*)d_in[12];
    const float* n2w  = (const float*)d_in[13];
    const float* n2b  = (const float*)d_in[14];
    const float* upw  = (const float*)d_in[15];
    const float* upb  = (const float*)d_in[16];
    const float* fw   = (const float*)d_in[17];
    const float* fb   = (const float*)d_in[18];
    float* out = (float*)d_out;

    const int smb = SM_FLOATS * 4;
    cudaFuncSetAttribute(k_persist, cudaFuncAttributeMaxDynamicSharedMemorySize, smb);

    int dev = 0;
    cudaGetDevice(&dev);
    int nsm = 0;
    cudaDeviceGetAttribute(&nsm, cudaDevAttrMultiProcessorCount, dev);
    int occ = 0;
    cudaOccupancyMaxActiveBlocksPerMultiprocessor(&occ, k_persist, NTHR, smb);
    if (occ < 1) occ = 1;
    int G = nsm * occ;
    if (G > NITEM) G = NITEM;

    k_persist<<<G, NTHR, smb>>>(G, xin, c1fw, c1fb, c1pw, c1pb,
                                cfw, cfb, cgw, cgb, c2w, c2b);
    k_final<<<(BB * LL) / 256, 256>>>(n1w, n1b, n2w, n2b, upw, upb, fw, fb, out);
}

// round 17
// speedup vs baseline: 1.0013x; 1.0013x over previous
#include <cuda_runtime.h>

// ---------------------------------------------------------------------------
// Persistent-kernel WaveNet stack (proven R13 k_persist) + R13 scalar final
// head (proven lowest-latency variant) with flag reset folded in.
// ---------------------------------------------------------------------------

#define S3   3
#define BB   8
#define CH   16
#define GC   32
#define LL   4096
#define RR   24          // S3*BB rows
#define TILE 128
#define NTHR 256
#define NSTG 33
#define NCHK 16          // chunks per row (256 positions each)
#define NITEM (NSTG * RR * NCHK)

typedef unsigned long long ull;

__device__ __forceinline__ ull dup2(float a) {
    ull r; asm("mov.b64 %0, {%1,%1};" : "=l"(r) : "f"(a)); return r;
}
__device__ __forceinline__ void upk(ull v, float &a, float &b) {
    asm("mov.b64 {%0,%1}, %2;" : "=f"(a), "=f"(b) : "l"(v));
}
__device__ __forceinline__ ull pk(float a, float b) {
    ull r; asm("mov.b64 %0, {%1,%2};" : "=l"(r) : "f"(a), "f"(b)); return r;
}
__device__ __forceinline__ ull f2fma(ull a, ull b, ull c) {
    ull r; asm("fma.rn.f32x2 %0, %1, %2, %3;" : "=l"(r) : "l"(a), "l"(b), "l"(c)); return r;
}
__device__ __forceinline__ float tanhap(float x) {
    float r; asm("tanh.approx.f32 %0, %1;" : "=f"(r) : "f"(x)); return r;
}
__device__ __forceinline__ float sigap(float x) {
    return fmaf(tanhap(x * 0.5f), 0.5f, 0.5f);
}
__device__ __forceinline__ int ld_acq(const int* p) {
    int v; asm volatile("ld.acquire.gpu.global.b32 %0, [%1];" : "=r"(v) : "l"(p) : "memory");
    return v;
}
__device__ __forceinline__ void st_rel(int* p, int v) {
    asm volatile("st.release.gpu.global.b32 [%0], %1;" :: "l"(p), "r"(v) : "memory");
}

// Residual stream 4-buffer ring + skip accumulator, [row][c][l]
__device__ float g_X4[4][RR * CH * LL];
__device__ float g_SK[RR * CH * LL];
__device__ int   g_flag[NITEM];      // zero-initialized at module load

// Shared layout (float offsets). Dup (ull) regions store each scalar twice.
#define O_WFD 0          // 2048  [oc][c][tap] dup
#define O_WGD 2048       // 2048
#define O_W2T 4096       // 1024  transposed [k][o] dup
#define O_W1D 5120       // 512   [o][c] dup
#define O_BFD 5632       // 64
#define O_BGD 5696       // 64
#define O_B2D 5760       // 32
#define O_B1D 5792       // 32
#define O_H   5824       // small: 16ch x 384 | large: 3 windows x 16ch x 128 (both 6144)
#define O_Z   11968      // 32 ch x 128 = 4096
#define SM_FLOATS 16064  // 64256 bytes

// ---------------------------------------------------------------------------
__global__ void __launch_bounds__(NTHR, 3) k_persist(
        int G,
        const float* __restrict__ xin,
        const float* __restrict__ c1fw, const float* __restrict__ c1fb,
        const float* __restrict__ c1pw, const float* __restrict__ c1pb,
        const float* __restrict__ cfw, const float* __restrict__ cfb,
        const float* __restrict__ cgw, const float* __restrict__ cgb,
        const float* __restrict__ c2w, const float* __restrict__ c2b) {
    extern __shared__ float sm[];
    int tid = threadIdx.x;

    for (int n = blockIdx.x; n < NITEM; n += G) {
        int stage = n / (RR * NCHK);
        int m = n - stage * (RR * NCHK);
        int row = m >> 4, chunk = m & 15;
        int s = row >> 3, bb = row & 7;
        int d = 1 << (stage % 11);
        int a = d >> 1;
        int t0 = chunk << 8;                 // 256 positions per chunk
        int first = (stage == 0);
        int small = (d <= 128);
        const float* Xsrc = g_X4[(stage + 3) & 3];
        float* Xdst       = g_X4[stage & 3];

        // ---- stage weights -> smem (duplicated, vectorized staging) ----
        {
            int wb = s * 33 + stage;
            const float* fsrc = cfw + wb * 1024;
            const float* gsrc = cgw + wb * 1024;
            ull* WFD = (ull*)(sm + O_WFD);
            ull* WGD = (ull*)(sm + O_WGD);
            {
                float4 f4 = *(const float4*)(fsrc + tid * 4);
                ulonglong2 u0, u1;
                u0.x = dup2(f4.x); u0.y = dup2(f4.y);
                u1.x = dup2(f4.z); u1.y = dup2(f4.w);
                *(ulonglong2*)(WFD + tid * 4)     = u0;
                *(ulonglong2*)(WFD + tid * 4 + 2) = u1;
                float4 g4 = *(const float4*)(gsrc + tid * 4);
                u0.x = dup2(g4.x); u0.y = dup2(g4.y);
                u1.x = dup2(g4.z); u1.y = dup2(g4.w);
                *(ulonglong2*)(WGD + tid * 4)     = u0;
                *(ulonglong2*)(WGD + tid * 4 + 2) = u1;
            }
            const float* w2src = c2w + wb * 512;
            ull* W2T = (ull*)(sm + O_W2T);
#pragma unroll
            for (int e = 0; e < 2; e++) {
                int idx = tid + e * 256;
                int k = idx >> 4, o = idx & 15;
                W2T[idx] = dup2(w2src[o * 32 + k]);
            }
            ull* W1D = (ull*)(sm + O_W1D);
            if (first) {
                if (tid < 16) {
                    W1D[tid] = dup2(c1fw[s * 16 + tid]);
                    ((ull*)(sm + O_B1D))[tid] = dup2(c1fb[s * 16 + tid]);
                }
            } else {
                int pbase = (s * 32 + (stage - 1));
                W1D[tid] = dup2(c1pw[pbase * 256 + tid]);
                if (tid < 16) ((ull*)(sm + O_B1D))[tid] = dup2(c1pb[pbase * 16 + tid]);
            }
            if (tid < 32) {
                ((ull*)(sm + O_BFD))[tid] = dup2(cfb[wb * 32 + tid]);
                ((ull*)(sm + O_BGD))[tid] = dup2(cgb[wb * 32 + tid]);
            }
            if (tid < 16) ((ull*)(sm + O_B2D))[tid] = dup2(c2b[wb * 16 + tid]);
        }

        // ---- dependency waits: PARALLEL flag polling by warp-0 lanes ----
        if (tid < 32) {
            int myflag = -1;
            if (!first && tid < 8) {
                // RAW on stage-1: lanes 0..7
                int lo_pos = t0 - a;
                int hi_pos = t0 + 255 + (d - a);
                if (lo_pos < 0) lo_pos = 0;
                if (hi_pos > LL - 1) hi_pos = LL - 1;
                int lo = lo_pos >> 8, hi = hi_pos >> 8;
                if (lo + tid <= hi)
                    myflag = ((stage - 1) * RR + row) * NCHK + lo + tid;
            } else if (stage >= 4 && tid >= 8 && tid < 24) {
                // WAR: stage-3 readers of buf[stage&3]: lanes 8..23
                int d3 = 1 << ((stage - 3) % 11);
                int a3 = d3 >> 1;
                int lo_pos = t0 - 255 - (d3 - a3);
                int hi_pos = t0 + 255 + a3;
                if (lo_pos < 0) lo_pos = 0;
                if (hi_pos > LL - 1) hi_pos = LL - 1;
                int lo = lo_pos >> 8, hi = hi_pos >> 8;
                int k = tid - 8;
                if (lo + k <= hi)
                    myflag = ((stage - 3) * RR + row) * NCHK + lo + k;
            } else if (stage >= 4 && tid == 24) {
                // WAW: stage-4 writer of the same chunk
                myflag = ((stage - 4) * RR + row) * NCHK + chunk;
            }
            if (myflag >= 0) {
                while (ld_acq(&g_flag[myflag]) == 0) __nanosleep(128);
            }
        }
        __syncthreads();

        if (small) {
            // ================= SMALL-d PATH (d <= 128) =================
            int npairs = (257 + d) >> 1;   // ceil((256+d)/2) <= 192
            if (tid < npairs) {
                int p = tid * 2;
                int pos0 = t0 - a + p;
                bool in0 = (unsigned)pos0 < LL;
                bool in1 = (unsigned)(pos0 + 1) < LL;
                float* hdst = sm + O_H + p;
                const ull* W1D = (const ull*)(sm + O_W1D);
                const ull* B1D = (const ull*)(sm + O_B1D);
                if (first) {
                    float x0 = in0 ? xin[(bb * LL + pos0) * 3 + s] : 0.f;
                    float x1 = in1 ? xin[(bb * LL + pos0 + 1) * 3 + s] : 0.f;
                    ull xv = pk(x0, x1);
#pragma unroll
                    for (int o = 0; o < 16; o++) {
                        ull r = f2fma(xv, W1D[o], B1D[o]);
                        float r0, r1; upk(r, r0, r1);
                        hdst[o * 384]     = in0 ? fmaxf(r0, 0.f) : 0.f;
                        hdst[o * 384 + 1] = in1 ? fmaxf(r1, 0.f) : 0.f;
                    }
                } else {
                    const float* Xr = Xsrc + row * CH * LL;
                    ull xv[16];
#pragma unroll
                    for (int c = 0; c < 16; c++) {
                        float x0 = in0 ? __ldcg(Xr + c * LL + pos0) : 0.f;
                        float x1 = in1 ? __ldcg(Xr + c * LL + pos0 + 1) : 0.f;
                        xv[c] = pk(x0, x1);
                    }
#pragma unroll
                    for (int o = 0; o < 16; o++) {
                        ull acc = B1D[o];
#pragma unroll
                        for (int c = 0; c < 16; c++)
                            acc = f2fma(xv[c], W1D[o * 16 + c], acc);
                        float r0, r1; upk(acc, r0, r1);
                        hdst[o * 384]     = in0 ? fmaxf(r0, 0.f) : 0.f;
                        hdst[o * 384 + 1] = in1 ? fmaxf(r1, 0.f) : 0.f;
                    }
                }
            }
            __syncthreads();

            int q = tid >> 5, pg = tid & 31;
            int ocb = q * 4, p4 = pg * 4;
            const ull* WF = (const ull*)(sm + O_WFD);
            const ull* WG = (const ull*)(sm + O_WGD);

            for (int sub = 0; sub < 2; sub++) {
                int soff = sub * 128;
                ull fA[4][2], gA[4][2];
#pragma unroll
                for (int ii = 0; ii < 4; ii++) {
                    ull fb = ((const ull*)(sm + O_BFD))[ocb + ii];
                    ull gb = ((const ull*)(sm + O_BGD))[ocb + ii];
                    fA[ii][0] = fb; fA[ii][1] = fb;
                    gA[ii][0] = gb; gA[ii][1] = gb;
                }
                if (d >= 4) {
#pragma unroll
                    for (int c = 0; c < 16; c++) {
                        const float* hb = sm + O_H + c * 384 + soff;
                        ulonglong2 hl = *(const ulonglong2*)(hb + p4);
                        ulonglong2 hr = *(const ulonglong2*)(hb + p4 + d);
#pragma unroll
                        for (int ii = 0; ii < 4; ii++) {
                            int wbase = ((ocb + ii) * 16 + c) * 2;
                            ulonglong2 wf = *(const ulonglong2*)(WF + wbase);
                            ulonglong2 wg = *(const ulonglong2*)(WG + wbase);
                            fA[ii][0] = f2fma(hl.x, wf.x, fA[ii][0]);
                            fA[ii][0] = f2fma(hr.x, wf.y, fA[ii][0]);
                            fA[ii][1] = f2fma(hl.y, wf.x, fA[ii][1]);
                            fA[ii][1] = f2fma(hr.y, wf.y, fA[ii][1]);
                            gA[ii][0] = f2fma(hl.x, wg.x, gA[ii][0]);
                            gA[ii][0] = f2fma(hr.x, wg.y, gA[ii][0]);
                            gA[ii][1] = f2fma(hl.y, wg.x, gA[ii][1]);
                            gA[ii][1] = f2fma(hr.y, wg.y, gA[ii][1]);
                        }
                    }
                } else {
#pragma unroll
                    for (int c = 0; c < 16; c++) {
                        const float* hb = sm + O_H + c * 384 + soff;
                        ulonglong2 hl = *(const ulonglong2*)(hb + p4);
                        ull b4 = *(const ull*)(hb + p4 + 4);
                        ulonglong2 hr;
                        if (d == 2) {
                            hr.x = hl.y; hr.y = b4;
                        } else {
                            float f0, f1, f2, f3, f4, f5;
                            upk(hl.x, f0, f1); upk(hl.y, f2, f3); upk(b4, f4, f5);
                            hr.x = pk(f1, f2); hr.y = pk(f3, f4);
                        }
#pragma unroll
                        for (int ii = 0; ii < 4; ii++) {
                            int wbase = ((ocb + ii) * 16 + c) * 2;
                            ulonglong2 wf = *(const ulonglong2*)(WF + wbase);
                            ulonglong2 wg = *(const ulonglong2*)(WG + wbase);
                            fA[ii][0] = f2fma(hl.x, wf.x, fA[ii][0]);
                            fA[ii][0] = f2fma(hr.x, wf.y, fA[ii][0]);
                            fA[ii][1] = f2fma(hl.y, wf.x, fA[ii][1]);
                            fA[ii][1] = f2fma(hr.y, wf.y, fA[ii][1]);
                            gA[ii][0] = f2fma(hl.x, wg.x, gA[ii][0]);
                            gA[ii][0] = f2fma(hr.x, wg.y, gA[ii][0]);
                            gA[ii][1] = f2fma(hl.y, wg.x, gA[ii][1]);
                            gA[ii][1] = f2fma(hr.y, wg.y, gA[ii][1]);
                        }
                    }
                }
#pragma unroll
                for (int ii = 0; ii < 4; ii++) {
                    float* zp = sm + O_Z + (ocb + ii) * 128 + p4;
                    float f0, f1, f2, f3, g0, g1, g2, g3;
                    upk(fA[ii][0], f0, f1); upk(fA[ii][1], f2, f3);
                    upk(gA[ii][0], g0, g1); upk(gA[ii][1], g2, g3);
                    float4 zv;
                    zv.x = tanhap(f0) * sigap(g0);
                    zv.y = tanhap(f1) * sigap(g1);
                    zv.z = tanhap(f2) * sigap(g2);
                    zv.w = tanhap(f3) * sigap(g3);
                    *(float4*)zp = zv;
                }
                __syncthreads();

                int o0 = q * 2;
                const ull* W2T = (const ull*)(sm + O_W2T);
                ull acc[2][2];
#pragma unroll
                for (int oi = 0; oi < 2; oi++) {
                    ull bv = ((const ull*)(sm + O_B2D))[o0 + oi];
                    acc[oi][0] = bv; acc[oi][1] = bv;
                }
#pragma unroll 8
                for (int k = 0; k < 32; k++) {
                    ulonglong2 zv = *(const ulonglong2*)(sm + O_Z + k * 128 + p4);
                    ulonglong2 w = *(const ulonglong2*)(W2T + k * 16 + o0);
                    acc[0][0] = f2fma(zv.x, w.x, acc[0][0]);
                    acc[0][1] = f2fma(zv.y, w.x, acc[0][1]);
                    acc[1][0] = f2fma(zv.x, w.y, acc[1][0]);
                    acc[1][1] = f2fma(zv.y, w.y, acc[1][1]);
                }
                float* SKg = g_SK + row * CH * LL;
#pragma unroll
                for (int oi = 0; oi < 2; oi++) {
                    int o = o0 + oi;
                    const float* hc = sm + O_H + o * 384 + soff + p4 + a;
                    float h0, h1, h2, h3;
                    if (a & 1) {
                        h0 = hc[0]; h1 = hc[1]; h2 = hc[2]; h3 = hc[3];
                    } else {
                        float u0a, u0b, u1a, u1b;
                        upk(*(const ull*)hc, u0a, u0b);
                        upk(*(const ull*)(hc + 2), u1a, u1b);
                        h0 = u0a; h1 = u0b; h2 = u1a; h3 = u1b;
                    }
                    float r0, r1, r2, r3;
                    upk(acc[oi][0], r0, r1); upk(acc[oi][1], r2, r3);
                    r0 = fmaxf(r0, 0.f); r1 = fmaxf(r1, 0.f);
                    r2 = fmaxf(r2, 0.f); r3 = fmaxf(r3, 0.f);
                    int gidx = (row * CH + o) * LL + t0 + soff + p4;
                    if (stage != NSTG - 1) {
                        float4 xv = make_float4(h0 + r0, h1 + r1, h2 + r2, h3 + r3);
                        __stcg((float4*)(Xdst + gidx), xv);
                    }
                    float* so = SKg + o * LL + t0 + soff + p4;
                    if (first) {
                        __stcg((float4*)so, make_float4(r0, r1, r2, r3));
                    } else {
                        float4 old = __ldcg((const float4*)so);
                        __stcg((float4*)so, make_float4(old.x + r0, old.y + r1, old.z + r2, old.w + r3));
                    }
                }
                __syncthreads();
            }
        } else {
            // ================= LARGE-d PATH (d > 128): per-tile 3 windows ======
            for (int sub = 0; sub < 2; sub++) {
                int t0s = t0 + sub * 128;
                if (tid < 192) {
                    int w = tid >> 6;
                    int p = (tid & 63) * 2;
                    int wstart = (w == 0) ? t0s - a : (w == 1) ? t0s + d - a : t0s;
                    int pos0 = wstart + p;
                    bool in0 = (unsigned)pos0 < LL;
                    bool in1 = (unsigned)(pos0 + 1) < LL;
                    float* hdst = sm + O_H + w * 2048 + p;
                    const ull* W1D = (const ull*)(sm + O_W1D);
                    const ull* B1D = (const ull*)(sm + O_B1D);
                    const float* Xr = Xsrc + row * CH * LL;
                    ull xv[16];
#pragma unroll
                    for (int c = 0; c < 16; c++) {
                        float x0 = in0 ? __ldcg(Xr + c * LL + pos0) : 0.f;
                        float x1 = in1 ? __ldcg(Xr + c * LL + pos0 + 1) : 0.f;
                        xv[c] = pk(x0, x1);
                    }
#pragma unroll
                    for (int o = 0; o < 16; o++) {
                        ull acc = B1D[o];
#pragma unroll
                        for (int c = 0; c < 16; c++)
                            acc = f2fma(xv[c], W1D[o * 16 + c], acc);
                        float r0, r1; upk(acc, r0, r1);
                        hdst[o * 128]     = in0 ? fmaxf(r0, 0.f) : 0.f;
                        hdst[o * 128 + 1] = in1 ? fmaxf(r1, 0.f) : 0.f;
                    }
                }
                __syncthreads();

                int q = tid >> 5, pg = tid & 31;
                int ocb = q * 4, p4 = pg * 4;
                const ull* WF = (const ull*)(sm + O_WFD);
                const ull* WG = (const ull*)(sm + O_WGD);

                ull fA[4][2], gA[4][2];
#pragma unroll
                for (int ii = 0; ii < 4; ii++) {
                    ull fb = ((const ull*)(sm + O_BFD))[ocb + ii];
                    ull gb = ((const ull*)(sm + O_BGD))[ocb + ii];
                    fA[ii][0] = fb; fA[ii][1] = fb;
                    gA[ii][0] = gb; gA[ii][1] = gb;
                }
#pragma unroll
                for (int c = 0; c < 16; c++) {
                    ulonglong2 hl = *(const ulonglong2*)(sm + O_H + c * 128 + p4);
                    ulonglong2 hr = *(const ulonglong2*)(sm + O_H + 2048 + c * 128 + p4);
#pragma unroll
                    for (int ii = 0; ii < 4; ii++) {
                        int wbase = ((ocb + ii) * 16 + c) * 2;
                        ulonglong2 wf = *(const ulonglong2*)(WF + wbase);
                        ulonglong2 wg = *(const ulonglong2*)(WG + wbase);
                        fA[ii][0] = f2fma(hl.x, wf.x, fA[ii][0]);
                        fA[ii][0] = f2fma(hr.x, wf.y, fA[ii][0]);
                        fA[ii][1] = f2fma(hl.y, wf.x, fA[ii][1]);
                        fA[ii][1] = f2fma(hr.y, wf.y, fA[ii][1]);
                        gA[ii][0] = f2fma(hl.x, wg.x, gA[ii][0]);
                        gA[ii][0] = f2fma(hr.x, wg.y, gA[ii][0]);
                        gA[ii][1] = f2fma(hl.y, wg.x, gA[ii][1]);
                        gA[ii][1] = f2fma(hr.y, wg.y, gA[ii][1]);
                    }
                }
#pragma unroll
                for (int ii = 0; ii < 4; ii++) {
                    float* zp = sm + O_Z + (ocb + ii) * 128 + p4;
                    float f0, f1, f2, f3, g0, g1, g2, g3;
                    upk(fA[ii][0], f0, f1); upk(fA[ii][1], f2, f3);
                    upk(gA[ii][0], g0, g1); upk(gA[ii][1], g2, g3);
                    float4 zv;
                    zv.x = tanhap(f0) * sigap(g0);
                    zv.y = tanhap(f1) * sigap(g1);
                    zv.z = tanhap(f2) * sigap(g2);
                    zv.w = tanhap(f3) * sigap(g3);
                    *(float4*)zp = zv;
                }
                __syncthreads();

                int o0 = q * 2;
                const ull* W2T = (const ull*)(sm + O_W2T);
                ull acc[2][2];
#pragma unroll
                for (int oi = 0; oi < 2; oi++) {
                    ull bv = ((const ull*)(sm + O_B2D))[o0 + oi];
                    acc[oi][0] = bv; acc[oi][1] = bv;
                }
#pragma unroll 8
                for (int k = 0; k < 32; k++) {
                    ulonglong2 zv = *(const ulonglong2*)(sm + O_Z + k * 128 + p4);
                    ulonglong2 w = *(const ulonglong2*)(W2T + k * 16 + o0);
                    acc[0][0] = f2fma(zv.x, w.x, acc[0][0]);
                    acc[0][1] = f2fma(zv.y, w.x, acc[0][1]);
                    acc[1][0] = f2fma(zv.x, w.y, acc[1][0]);
                    acc[1][1] = f2fma(zv.y, w.y, acc[1][1]);
                }
                float* SKg = g_SK + row * CH * LL;
#pragma unroll
                for (int oi = 0; oi < 2; oi++) {
                    int o = o0 + oi;
                    float4 hv = *(const float4*)(sm + O_H + 4096 + o * 128 + p4);
                    float r0, r1, r2, r3;
                    upk(acc[oi][0], r0, r1); upk(acc[oi][1], r2, r3);
                    r0 = fmaxf(r0, 0.f); r1 = fmaxf(r1, 0.f);
                    r2 = fmaxf(r2, 0.f); r3 = fmaxf(r3, 0.f);
                    if (stage != NSTG - 1) {
                        float4 xv = make_float4(hv.x + r0, hv.y + r1, hv.z + r2, hv.w + r3);
                        __stcg((float4*)(Xdst + (row * CH + o) * LL + t0s + p4), xv);
                    }
                    float* so = SKg + o * LL + t0s + p4;
                    float4 old = __ldcg((const float4*)so);
                    __stcg((float4*)so, make_float4(old.x + r0, old.y + r1, old.z + r2, old.w + r3));
                }
                __syncthreads();
            }
        }

        // ---- publish ----
        if (tid == 0) st_rel(&g_flag[(stage * RR + row) * NCHK + chunk], 1);
    }
}

// ---------------------------------------------------------------------------
// PinSage + final head (per position, R13 scalar variant) + flag reset
// ---------------------------------------------------------------------------
__global__ void __launch_bounds__(128) k_final(const float* __restrict__ n1w,
                                               const float* __restrict__ n1b,
                                               const float* __restrict__ n2w,
                                               const float* __restrict__ n2b,
                                               const float* __restrict__ upw,
                                               const float* __restrict__ upb,
                                               const float* __restrict__ fw,
                                               const float* __restrict__ fb,
                                               float* __restrict__ out) {
    __shared__ float s_n1w[768], s_n2w[768], s_n1b[48], s_n2b[48];
    __shared__ float s_upw[6144], s_upb[192], s_fw[64], s_fb;
    int tid = threadIdx.x;
    int gi = blockIdx.x * 128 + tid;

    // reset dependency flags for the next replay (stream-ordered before the
    // next k_persist launch; g_flag zero-init covers the very first run).
    // 256 blocks x 128 thr = 32768 slots >= NITEM; each resets up to 1 flag.
    if (gi < NITEM) g_flag[gi] = 0;

    for (int idx = tid; idx < 768; idx += 128) { s_n1w[idx] = n1w[idx]; s_n2w[idx] = n2w[idx]; }
    for (int idx = tid; idx < 6144; idx += 128) s_upw[idx] = upw[idx];
    if (tid < 48) { s_n1b[tid] = n1b[tid]; s_n2b[tid] = n2b[tid]; }
    for (int idx = tid; idx < 192; idx += 128) s_upb[idx] = upb[idx];
    if (tid < 64) s_fw[tid] = fw[tid];
    if (tid == 0) s_fb = fb[0];
    __syncthreads();

    int b = gi >> 12, l = gi & 4095;

    float F[3][16];
#pragma unroll
    for (int s = 0; s < 3; s++) {
        const float* sk = g_SK + (s * 8 + b) * CH * LL;
#pragma unroll
        for (int c = 0; c < 16; c++) F[s][c] = fmaxf(sk[c * LL + l], 0.f);
    }

    float m[64];
#pragma unroll
    for (int o = 0; o < 64; o++) m[o] = 0.f;

#pragma unroll
    for (int s = 0; s < 3; s++) {
        int n1 = (s == 0) ? 1 : 0;
        int n2 = (s == 2) ? 1 : 2;
        float nb[16];
#pragma unroll
        for (int o = 0; o < 16; o++) {
            float a1 = s_n1b[s * 16 + o], a2 = s_n2b[s * 16 + o];
#pragma unroll
            for (int c = 0; c < 16; c++) {
                a1 = fmaf(s_n1w[(s * 16 + o) * 16 + c], F[n1][c], a1);
                a2 = fmaf(s_n2w[(s * 16 + o) * 16 + c], F[n2][c], a2);
            }
            nb[o] = fmaxf(fmaxf(a1, 0.f), fmaxf(a2, 0.f));
        }
#pragma unroll 8
        for (int o = 0; o < 64; o++) {
            const float* wr = s_upw + (s * 64 + o) * 32;
            float u = s_upb[s * 64 + o];
#pragma unroll
            for (int c = 0; c < 16; c++) u = fmaf(wr[c], F[s][c], u);
#pragma unroll
            for (int c = 0; c < 16; c++) u = fmaf(wr[16 + c], nb[c], u);
            m[o] = fmaxf(m[o], fmaxf(u, 0.f));
        }
    }
    float logit = s_fb;
#pragma unroll
    for (int o = 0; o < 64; o++) logit = fmaf(s_fw[o], m[o], logit);
    out[gi] = fmaf(tanhap(logit * 0.5f), 0.5f, 0.5f);
}

// ---------------------------------------------------------------------------
extern "C" void kernel_launch(void* const* d_in, const int* in_sizes, int n_in,
                              void* d_out, int out_size) {
    const float* xin  = (const float*)d_in[0];
    const float* c1fw = (const float*)d_in[1];
    const float* c1fb = (const float*)d_in[2];
    const float* c1pw = (const float*)d_in[3];
    const float* c1pb = (const float*)d_in[4];
    const float* cfw  = (const float*)d_in[5];
    const float* cfb  = (const float*)d_in[6];
    const float* cgw  = (const float*)d_in[7];
    const float* cgb  = (const float*)d_in[8];
    const float* c2w  = (const float*)d_in[9];
    const float* c2b  = (const float*)d_in[10];
    const float* n1w  = (const float*)d_in[11];
    const float* n1b  = (const float*)d_in[12];
    const float* n2w  = (const float*)d_in[13];
    const float* n2b  = (const float*)d_in[14];
    const float* upw  = (const float*)d_in[15];
    const float* upb  = (const float*)d_in[16];
    const float* fw   = (const float*)d_in[17];
    const float* fb   = (const float*)d_in[18];
    float* out = (float*)d_out;

    const int smb = SM_FLOATS * 4;
    cudaFuncSetAttribute(k_persist, cudaFuncAttributeMaxDynamicSharedMemorySize, smb);

    int dev = 0;
    cudaGetDevice(&dev);
    int nsm = 0;
    cudaDeviceGetAttribute(&nsm, cudaDevAttrMultiProcessorCount, dev);
    int occ = 0;
    cudaOccupancyMaxActiveBlocksPerMultiprocessor(&occ, k_persist, NTHR, smb);
    if (occ < 1) occ = 1;
    int G = nsm * occ;
    if (G > NITEM) G = NITEM;

    k_persist<<<G, NTHR, smb>>>(G, xin, c1fw, c1fb, c1pw, c1pb,
                                cfw, cfb, cgw, cgb, c2w, c2b);
    k_final<<<(BB * LL) / 128, 128>>>(n1w, n1b, n2w, n2b, upw, upb, fw, fb, out);
}